// round 15
// baseline (speedup 1.0000x reference)
#include <cuda_runtime.h>
#include <cstdint>

// SSIM 1-D loss via mma.sync.m16n8k8 tf32 (sm_100 base target).
// Grid (47, 512): CTA = 1024 outputs of one row, 256 threads = 8 warps.
// Warp strip = 128 outputs = 2 segments x 64 positions = 4 m-blocks of 16.
//   A[16x32 per m-block] = banded Gaussian, W(k-m+5); block-banded staircase:
//   m-block j uses k rel [16j-8, 16j+24) -> K-chunks c=2j..2j+3 (8 wide).
//   B[k x n8]: n = 4 channels (u, v, u^2, v^2) x 2 segments; chunks shared
//   between adjacent m-blocks -> 10 B fragments, 16 mma per warp.
// Staging: float4 (u,v,u2,v2) per position, tf32-rounded (cvt.rna), padded
//   +64B per 64 positions for conflict-free B-fragment LDS.
// Epilogue: shfl.xor(1) pairs (U,V)<->(P,Q), 4 SSIM/thread, valid-count.
// Reduction: g_part + atomicInc last-block tail (self-resetting).

#define TT      48000
#define NROWS   512
#define TILEO   1024
#define NTILE   47              // 47*1024 = 48128 >= 48000
#define NCTA    (NTILE * NROWS) // 24064
#define TPB     256
#define NSTAGE  1040            // logical l = global - (tileStart - 8), [0,1040)
#define STGB    (NSTAGE * 16 + (NSTAGE / 64 + 1) * 64)
#define C1F     1.0e-4f
#define C2F     9.0e-4f
#define CCF     (C1F + C2F)

__device__ __align__(16) float g_part[NCTA];
__device__ unsigned int g_cnt = 0;

// tf32 destination of cvt is a .b32 register (ptxas rejects "=f" here).
__device__ __forceinline__ float tf32r(float x) {
    uint32_t r;
    asm("cvt.rna.tf32.f32 %0, %1;" : "=r"(r) : "f"(x));
    return __uint_as_float(r);
}
// Gaussian(11, sigma 1.5) normalized: W(d) = 0.26601158 * exp(-(d-5)^2/4.5)
__device__ __forceinline__ uint32_t wgt(int d) {
    if (d < 0 || d > 10) return 0u;
    float dd = (float)(d - 5);
    return __float_as_uint(tf32r(0.26601158f * __expf(dd * dd * (-1.0f / 4.5f))));
}
__device__ __forceinline__ void mma8(float& d0, float& d1, float& d2, float& d3,
                                     uint32_t a0, uint32_t a1, uint32_t a2,
                                     uint32_t a3, uint32_t b0, uint32_t b1) {
    asm volatile(
        "mma.sync.aligned.m16n8k8.row.col.f32.tf32.tf32.f32 "
        "{%0,%1,%2,%3}, {%4,%5,%6,%7}, {%8,%9}, {%0,%1,%2,%3};"
        : "+f"(d0), "+f"(d1), "+f"(d2), "+f"(d3)
        : "r"(a0), "r"(a1), "r"(a2), "r"(a3), "r"(b0), "r"(b1));
}
__device__ __forceinline__ int physb(int l) {        // byte offset of position l
    return (l << 4) + ((l >> 6) << 6);
}

__global__ __launch_bounds__(TPB) void ssim_mma(const float* __restrict__ pred,
                                                const float* __restrict__ tgt,
                                                float* __restrict__ out) {
    __shared__ __align__(16) char stg[STGB];
    __shared__ float  wsum[TPB / 32];
    __shared__ double dsh[TPB / 32];
    __shared__ int    isLast;

    const int tid  = threadIdx.x;
    const int wid  = tid >> 5;
    const int lane = tid & 31;
    const int tig  = lane & 3;            // thread-in-group
    const int gid  = lane >> 2;           // group id 0..7
    const int tile = blockIdx.x;
    const int row  = blockIdx.y;
    const int tileStart = tile * TILEO;
    const long rowBase  = (long)row * TT;

    // ---- stage (u, v, u2, v2) float4 per position, tf32-rounded ----
    for (int q = tid; q < NSTAGE / 4; q += TPB) {
        int l0 = q * 4;
        int g0 = tileStart - 8 + l0;
        float p[4], t[4];
        if (g0 >= 0 && g0 + 4 <= TT) {
            float4 pp = *reinterpret_cast<const float4*>(pred + rowBase + g0);
            float4 tt = *reinterpret_cast<const float4*>(tgt  + rowBase + g0);
            p[0]=pp.x; p[1]=pp.y; p[2]=pp.z; p[3]=pp.w;
            t[0]=tt.x; t[1]=tt.y; t[2]=tt.z; t[3]=tt.w;
        } else {
#pragma unroll
            for (int e = 0; e < 4; e++) {
                int g = g0 + e;
                bool in = (g >= 0 && g < TT);
                p[e] = in ? pred[rowBase + g] : 0.0f;
                t[e] = in ? tgt [rowBase + g] : 0.0f;
            }
        }
#pragma unroll
        for (int e = 0; e < 4; e++) {
            float uu = p[e] + t[e], vv = p[e] - t[e];
            float4 sv = make_float4(tf32r(uu), tf32r(vv),
                                    tf32r(uu * uu), tf32r(vv * vv));
            *reinterpret_cast<float4*>(stg + physb(l0 + e)) = sv;
        }
    }
    __syncthreads();

    // ---- A fragments (banded weights), 4 K-steps ----
    uint32_t af[4][4];
#pragma unroll
    for (int s = 0; s < 4; s++) {
        int d0 = 8 * s + tig - gid - 3;
        af[s][0] = wgt(d0);
        af[s][1] = wgt(d0 - 8);
        af[s][2] = wgt(d0 + 4);
        af[s][3] = wgt(d0 - 4);
    }

    // ---- B fragments: 10 chunks; n = gid -> ch = gid&3, seg = gid>>2 ----
    const int ch   = gid & 3;
    const int segB = gid >> 2;
    const int lbase = 8 + wid * 128 + segB * 64;
    uint32_t bf[10][2];
#pragma unroll
    for (int c = 0; c < 10; c++) {
        int l0 = lbase + 8 * c - 8 + tig;
        bf[c][0] = __float_as_uint(
            *reinterpret_cast<const float*>(stg + physb(l0) + ch * 4));
        bf[c][1] = __float_as_uint(
            *reinterpret_cast<const float*>(stg + physb(l0 + 4) + ch * 4));
    }

    // ---- 16 mma: 4 m-blocks x 4 K-steps (chunk = 2j + s) ----
    float acc[4][4];
#pragma unroll
    for (int j = 0; j < 4; j++) { acc[j][0]=0.f; acc[j][1]=0.f; acc[j][2]=0.f; acc[j][3]=0.f; }
#pragma unroll
    for (int j = 0; j < 4; j++)
#pragma unroll
        for (int s = 0; s < 4; s++)
            mma8(acc[j][0], acc[j][1], acc[j][2], acc[j][3],
                 af[s][0], af[s][1], af[s][2], af[s][3],
                 bf[2 * j + s][0], bf[2 * j + s][1]);

    // ---- epilogue: pair exchange, 1 SSIM per thread per m-block ----
    const int odd  = tig & 1;
    const int segE = tig >> 1;
    float ssum = 0.0f;
    int   vcnt = 0;
#pragma unroll
    for (int j = 0; j < 4; j++) {
        float pc0 = __shfl_xor_sync(0xffffffffu, acc[j][0], 1);
        float pc1 = __shfl_xor_sync(0xffffffffu, acc[j][1], 1);
        float pc2 = __shfl_xor_sync(0xffffffffu, acc[j][2], 1);
        float pc3 = __shfl_xor_sync(0xffffffffu, acc[j][3], 1);
        float U = odd ? pc2       : acc[j][0];
        float V = odd ? pc3       : acc[j][1];
        float P = odd ? acc[j][2] : pc0;
        float Q = odd ? acc[j][3] : pc1;

        float U2 = U * U;
        float V2 = V * V;
        float t1 = fmaf(0.5f, U2, C1F);
        float a2 = fmaf(-0.5f, V2, t1);                 // 2 mu1 mu2 + C1
        float b2 = fmaf( 0.5f, V2, t1);                 // mu1^2+mu2^2 + C1
        float c2 = fmaf(0.5f, P, fmaf(-0.5f, Q, CCF - a2));
        float d2 = fmaf(0.5f, P, fmaf( 0.5f, Q, CCF - b2));
        float ssim = __fdividef(a2 * c2, b2 * d2);

        int gpos = tileStart + wid * 128 + segE * 64 + j * 16 + gid + (odd ? 8 : 0);
        if (gpos < TT) { ssum += ssim; vcnt++; }
    }
    float lsum = (float)vcnt - ssum;

    // ---- block reduce ----
#pragma unroll
    for (int off = 16; off; off >>= 1)
        lsum += __shfl_down_sync(0xffffffffu, lsum, off);
    if (lane == 0) wsum[wid] = lsum;
    __syncthreads();

    const int bid = blockIdx.y * NTILE + blockIdx.x;
    if (tid < 32) {
        float v2 = (tid < TPB / 32) ? wsum[tid] : 0.0f;
#pragma unroll
        for (int off = 4; off; off >>= 1)
            v2 += __shfl_down_sync(0xffffffffu, v2, off);
        if (tid == 0) {
            g_part[bid] = v2;
            __threadfence();
            unsigned int old = atomicInc(&g_cnt, NCTA - 1u);
            isLast = (old == NCTA - 1u) ? 1 : 0;
        }
    }
    __syncthreads();

    // ---- last block reduces all partials ----
    if (isLast) {
        double ds = 0.0;
        const float4* gp4 = reinterpret_cast<const float4*>(g_part);
        for (int k = tid; k < NCTA / 4; k += TPB) {
            float4 q = gp4[k];
            ds += (double)((q.x + q.y) + (q.z + q.w));
        }
#pragma unroll
        for (int off = 16; off; off >>= 1)
            ds += __shfl_down_sync(0xffffffffu, ds, off);
        if (lane == 0) dsh[wid] = ds;
        __syncthreads();
        if (tid == 0) {
            double tot = 0.0;
#pragma unroll
            for (int i = 0; i < TPB / 32; i++) tot += dsh[i];
            out[0] = (float)(tot / (double)((long long)NROWS * TT));
        }
    }
}

extern "C" void kernel_launch(void* const* d_in, const int* in_sizes, int n_in,
                              void* d_out, int out_size) {
    (void)in_sizes; (void)n_in; (void)out_size;
    const float* pred = (const float*)d_in[0];
    const float* tgt  = (const float*)d_in[1];
    dim3 grid(NTILE, NROWS);
    ssim_mma<<<grid, TPB>>>(pred, tgt, (float*)d_out);
}